// round 13
// baseline (speedup 1.0000x reference)
#include <cuda_runtime.h>

// Problem constants
#define Bn    4
#define Cc    256
#define HF    128
#define WF    128
#define Sx    64
#define CROPS_ELEMS ((size_t)128 * Cc * Sx * Sx)   // 134217728
#define TROW  260                                  // tile row stride (64 chunks*4 + 4 pad)

// Scratch: feat transposed to NHWC [b][y][x][c], c contiguous (67 MB)
__device__ float g_nhwc[(size_t)Bn * HF * WF * Cc];

__device__ __forceinline__ void roi_params(const float* __restrict__ obb, int r,
                                           float& cx, float& cy, float& wf, float& hf,
                                           float& c_, float& s_) {
    const float* o = obb + r * 5;
    cx = o[0] * 0.125f;
    cy = o[1] * 0.125f;
    wf = fmaxf(o[2], 1.0f) * (1.25f / 8.0f);
    hf = fmaxf(o[3], 1.0f) * (1.25f / 8.0f);
    float ang = o[4] * 0.017453292519943295f;  // deg2rad
    c_ = cosf(ang);
    s_ = sinf(ang);
}

// ---------------------------------------------------------------------------
// Kernel 1: NCHW -> NHWC transpose, 4 y-rows per block (MLP=4). Proven.
// ---------------------------------------------------------------------------
__global__ __launch_bounds__(256) void transpose_kernel(const float* __restrict__ feat)
{
    __shared__ float ts[4][32 * 33];
    const int tx = threadIdx.x;       // 0..7
    const int ty = threadIdx.y;       // 0..31
    const int bz = blockIdx.z;        // 0..127
    const int b = bz >> 5;
    const int ybase = (bz & 31) * 4;

    const int c = blockIdx.y * 32 + ty;
    const float4* feat4 = reinterpret_cast<const float4*>(feat);
    const size_t rowbase = (size_t)(b * Cc + c) * HF;

    float4 v[4];
    #pragma unroll
    for (int k = 0; k < 4; ++k)
        v[k] = __ldcs(&feat4[(rowbase + ybase + k) * (WF / 4) + blockIdx.x * 8 + tx]);

    #pragma unroll
    for (int k = 0; k < 4; ++k) {
        ts[k][(4 * tx + 0) * 33 + ty] = v[k].x;
        ts[k][(4 * tx + 1) * 33 + ty] = v[k].y;
        ts[k][(4 * tx + 2) * 33 + ty] = v[k].z;
        ts[k][(4 * tx + 3) * 33 + ty] = v[k].w;
    }
    __syncthreads();

    float4* nh4 = reinterpret_cast<float4*>(g_nhwc);
    const int x = blockIdx.x * 32 + ty;
    #pragma unroll
    for (int k = 0; k < 4; ++k) {
        float4 o;
        o.x = ts[k][ty * 33 + 4 * tx + 0];
        o.y = ts[k][ty * 33 + 4 * tx + 1];
        o.z = ts[k][ty * 33 + 4 * tx + 2];
        o.w = ts[k][ty * 33 + 4 * tx + 3];
        nh4[((size_t)(b * HF + ybase + k) * WF + x) * (Cc / 4) + blockIdx.y * 8 + tx] = o;
    }
}

// ---------------------------------------------------------------------------
// Kernel 2: pooling + M_all. One block per (roi, sy): 512 threads.
// Single compute+store pass over all 256 channels (2 barriers total).
// Warp w: points (w>>1)*8..+7, chunks co = 32*(w&1)+lane (64 chunks/pixel).
// Hot loop = proven R8 advance-only pipelined tap-reuse, unchanged.
// ---------------------------------------------------------------------------
__global__ __launch_bounds__(512, 2) void rotated_roi_pool_kernel(
    const float* __restrict__ obb,
    float* __restrict__ out)
{
    extern __shared__ float dsm[];
    int*   o00  = reinterpret_cast<int*>(dsm);
    int*   o01  = o00 + Sx;
    int*   o10  = o01 + Sx;
    int*   o11  = o10 + Sx;
    float* w00s = dsm + 4 * Sx;
    float* w01s = w00s + Sx;
    float* w10s = w01s + Sx;
    float* w11s = w10s + Sx;
    float* tile = dsm + 8 * Sx;     // [64 points][TROW floats]

    const int t    = threadIdx.x;
    const int sy   = blockIdx.x;
    const int r    = blockIdx.y;
    const int b    = r >> 5;
    const int warp = t >> 5;
    const int lane = t & 31;

    // ---- Phase 0: per-sample-point coordinates ----
    if (t < Sx) {
        const int sx = t;
        float cx, cy, wf, hf, c_, s_;
        roi_params(obb, r, cx, cy, wf, hf, c_, s_);

        const float sxs = wf * (2.0f / (float)WF);
        const float sys = hf * (2.0f / (float)HF);
        const float txc = cx * (2.0f / (float)WF) - 1.0f;
        const float tyc = cy * (2.0f / (float)HF) - 1.0f;
        const float a11 = c_ * sxs, a12 = -s_ * sys;
        const float a21 = s_ * sxs, a22 =  c_ * sys;

        const float X = 2.0f * ((float)sx + 0.5f) / (float)Sx - 1.0f;
        const float Y = 2.0f * ((float)sy + 0.5f) / (float)Sx - 1.0f;

        const float gx = a11 * X + a12 * Y + txc;
        const float gy = a21 * X + a22 * Y + tyc;

        const float ix = ((gx + 1.0f) * (float)WF - 1.0f) * 0.5f;
        const float iy = ((gy + 1.0f) * (float)HF - 1.0f) * 0.5f;

        const float x0f = floorf(ix);
        const float y0f = floorf(iy);
        const float wx = ix - x0f;
        const float wy = iy - y0f;

        const int x0 = (int)x0f, y0 = (int)y0f;
        const int x1 = x0 + 1,   y1 = y0 + 1;

        const float vx0 = (x0 >= 0 && x0 < WF) ? 1.0f : 0.0f;
        const float vx1 = (x1 >= 0 && x1 < WF) ? 1.0f : 0.0f;
        const float vy0 = (y0 >= 0 && y0 < HF) ? 1.0f : 0.0f;
        const float vy1 = (y1 >= 0 && y1 < HF) ? 1.0f : 0.0f;

        w00s[sx] = (1.0f - wx) * (1.0f - wy) * vx0 * vy0;
        w01s[sx] = wx          * (1.0f - wy) * vx1 * vy0;
        w10s[sx] = (1.0f - wx) * wy          * vx0 * vy1;
        w11s[sx] = wx          * wy          * vx1 * vy1;

        const int xc0 = min(max(x0, 0), WF - 1);
        const int xc1 = min(max(x1, 0), WF - 1);
        const int yc0 = min(max(y0, 0), HF - 1);
        const int yc1 = min(max(y1, 0), HF - 1);

        const int base = b * HF * WF;  // pixels
        o00[sx] = (base + yc0 * WF + xc0) * (Cc / 4);
        o01[sx] = (base + yc0 * WF + xc1) * (Cc / 4);
        o10[sx] = (base + yc1 * WF + xc0) * (Cc / 4);
        o11[sx] = (base + yc1 * WF + xc1) * (Cc / 4);
    }
    __syncthreads();

    const float4* __restrict__ nhwc4 = reinterpret_cast<const float4*>(g_nhwc);
    const int ibase = (warp >> 1) * 8;          // 8 points per warp-pair slot
    const int co    = 32 * (warp & 1) + lane;   // float4 chunk 0..63

    // ---- compute phase: pipelined tap-reuse (R8 hot loop) ----
    {
        int p00 = o00[ibase], p01 = o01[ibase], p10 = o10[ibase], p11 = o11[ibase];
        float4 c00 = __ldg(&nhwc4[p00 + co]);
        float4 c01 = __ldg(&nhwc4[p01 + co]);
        float4 c10 = __ldg(&nhwc4[p10 + co]);
        float4 c11 = __ldg(&nhwc4[p11 + co]);

        #pragma unroll
        for (int j = 0; j < 8; ++j) {
            const int i = ibase + j;

            // Issue loads for point i+1 (consumed next iteration)
            float4 n00, n01, n10, n11;
            int mode = 0;
            if (j < 7) {
                const int u00 = o00[i + 1], u01 = o01[i + 1];
                const int u10 = o10[i + 1], u11 = o11[i + 1];
                if (u00 == p00 && u01 == p01 && u10 == p10 && u11 == p11) {
                    mode = 0;
                } else if (u00 == p01 && u10 == p11) {
                    n01 = __ldg(&nhwc4[u01 + co]);
                    n11 = __ldg(&nhwc4[u11 + co]);
                    mode = 1;
                } else if (u00 == p10 && u01 == p11) {
                    n10 = __ldg(&nhwc4[u10 + co]);
                    n11 = __ldg(&nhwc4[u11 + co]);
                    mode = 2;
                } else {
                    n00 = __ldg(&nhwc4[u00 + co]);
                    n01 = __ldg(&nhwc4[u01 + co]);
                    n10 = __ldg(&nhwc4[u10 + co]);
                    n11 = __ldg(&nhwc4[u11 + co]);
                    mode = 3;
                }
                p00 = u00; p01 = u01; p10 = u10; p11 = u11;
            }

            const float a = w00s[i], b_ = w01s[i], c2 = w10s[i], d = w11s[i];
            float4 v;
            v.x = fmaf(d, c11.x, fmaf(c2, c10.x, fmaf(b_, c01.x, a * c00.x)));
            v.y = fmaf(d, c11.y, fmaf(c2, c10.y, fmaf(b_, c01.y, a * c00.y)));
            v.z = fmaf(d, c11.z, fmaf(c2, c10.z, fmaf(b_, c01.z, a * c00.z)));
            v.w = fmaf(d, c11.w, fmaf(c2, c10.w, fmaf(b_, c01.w, a * c00.w)));
            *reinterpret_cast<float4*>(&tile[i * TROW + 4 * co]) = v;

            if (j < 7) {
                if (mode == 1)      { c00 = c01; c10 = c11; c01 = n01; c11 = n11; }
                else if (mode == 2) { c00 = c10; c01 = c11; c10 = n10; c11 = n11; }
                else if (mode == 3) { c00 = n00; c01 = n01; c10 = n10; c11 = n11; }
            }
        }
    }
    __syncthreads();

    // ---- store phase: lanes = sx, coalesced streaming stores ----
    {
        const int sx_st = t & 63;   // sx
        const int cg    = t >> 6;   // channel group 0..7 (8 chunks each)
        #pragma unroll
        for (int j = 0; j < 8; ++j) {
            const int chunk = cg * 8 + j;          // 0..63
            float4 v = *reinterpret_cast<const float4*>(&tile[sx_st * TROW + 4 * chunk]);
            const int c_global = 4 * chunk;
            float* op = out + (((size_t)(r * Cc + c_global) * Sx + sy) * Sx) + sx_st;
            __stcs(op,               v.x);
            __stcs(op + 1 * Sx * Sx, v.y);
            __stcs(op + 2 * Sx * Sx, v.z);
            __stcs(op + 3 * Sx * Sx, v.w);
        }
    }

    // ---- M_all (folded): block (sy==0, r), one thread ----
    if (sy == 0 && t == 0) {
        float cx, cy, wf, hf, c_, s_;
        roi_params(obb, r, cx, cy, wf, hf, c_, s_);
        const float A  =  c_ * (wf / (float)Sx);
        const float Bv = -s_ * (hf / (float)Sx);
        const float A2 =  s_ * (wf / (float)Sx);
        const float B2 =  c_ * (hf / (float)Sx);
        const float Cx = cx - 0.5f * (float)Sx * (A + Bv);
        const float Cy = cy - 0.5f * (float)Sx * (A2 + B2);
        float* o = out + CROPS_ELEMS + (size_t)r * 6;
        o[0] = A;  o[1] = Bv; o[2] = Cx;
        o[3] = A2; o[4] = B2; o[5] = Cy;
    }
}

extern "C" void kernel_launch(void* const* d_in, const int* in_sizes, int n_in,
                              void* d_out, int out_size) {
    const float* feat = (const float*)d_in[0];
    const float* obb  = (const float*)d_in[1];
    float* out = (float*)d_out;

    const int pool_smem = (8 * Sx + Sx * TROW) * sizeof(float);  // ~67 KB
    cudaFuncSetAttribute(rotated_roi_pool_kernel,
                         cudaFuncAttributeMaxDynamicSharedMemorySize, pool_smem);

    dim3 tb(8, 32, 1);
    dim3 tg(WF / 32, Cc / 32, Bn * HF / 4);   // (4, 8, 128)
    transpose_kernel<<<tg, tb>>>(feat);

    dim3 grid(Sx, 128, 1);                    // (sy, roi)
    rotated_roi_pool_kernel<<<grid, 512, pool_smem>>>(obb, out);
}

// round 14
// speedup vs baseline: 1.0270x; 1.0270x over previous
#include <cuda_runtime.h>

// Problem constants
#define Bn    4
#define Cc    256
#define HF    128
#define WF    128
#define Sx    64
#define NPTS  128                                  // 2 sy rows x 64 sx per block
#define CROPS_ELEMS ((size_t)128 * Cc * Sx * Sx)   // 134217728

// Scratch: feat transposed to NHWC [b][y][x][c], c contiguous (67 MB)
__device__ float g_nhwc[(size_t)Bn * HF * WF * Cc];

__device__ __forceinline__ void roi_params(const float* __restrict__ obb, int r,
                                           float& cx, float& cy, float& wf, float& hf,
                                           float& c_, float& s_) {
    const float* o = obb + r * 5;
    cx = o[0] * 0.125f;
    cy = o[1] * 0.125f;
    wf = fmaxf(o[2], 1.0f) * (1.25f / 8.0f);
    hf = fmaxf(o[3], 1.0f) * (1.25f / 8.0f);
    float ang = o[4] * 0.017453292519943295f;  // deg2rad
    c_ = cosf(ang);
    s_ = sinf(ang);
}

// ---------------------------------------------------------------------------
// Kernel 1: NCHW -> NHWC transpose, 4 y-rows per block (MLP=4). Proven.
// ---------------------------------------------------------------------------
__global__ __launch_bounds__(256) void transpose_kernel(const float* __restrict__ feat)
{
    __shared__ float ts[4][32 * 33];
    const int tx = threadIdx.x;       // 0..7
    const int ty = threadIdx.y;       // 0..31
    const int bz = blockIdx.z;        // 0..127
    const int b = bz >> 5;
    const int ybase = (bz & 31) * 4;

    const int c = blockIdx.y * 32 + ty;
    const float4* feat4 = reinterpret_cast<const float4*>(feat);
    const size_t rowbase = (size_t)(b * Cc + c) * HF;

    float4 v[4];
    #pragma unroll
    for (int k = 0; k < 4; ++k)
        v[k] = __ldcs(&feat4[(rowbase + ybase + k) * (WF / 4) + blockIdx.x * 8 + tx]);

    #pragma unroll
    for (int k = 0; k < 4; ++k) {
        ts[k][(4 * tx + 0) * 33 + ty] = v[k].x;
        ts[k][(4 * tx + 1) * 33 + ty] = v[k].y;
        ts[k][(4 * tx + 2) * 33 + ty] = v[k].z;
        ts[k][(4 * tx + 3) * 33 + ty] = v[k].w;
    }
    __syncthreads();

    float4* nh4 = reinterpret_cast<float4*>(g_nhwc);
    const int x = blockIdx.x * 32 + ty;
    #pragma unroll
    for (int k = 0; k < 4; ++k) {
        float4 o;
        o.x = ts[k][ty * 33 + 4 * tx + 0];
        o.y = ts[k][ty * 33 + 4 * tx + 1];
        o.z = ts[k][ty * 33 + 4 * tx + 2];
        o.w = ts[k][ty * 33 + 4 * tx + 3];
        nh4[((size_t)(b * HF + ybase + k) * WF + x) * (Cc / 4) + blockIdx.y * 8 + tx] = o;
    }
}

// ---------------------------------------------------------------------------
// Kernel 2: pooling + M_all. One block per (roi, sy-pair): 256 threads.
// grid (32, 128): halves wave count vs (64, 128). Phase 0 computes 128
// points; compute/store sub-phases per (slab, row) use the PROVEN R8 hot
// loop unchanged.
// ---------------------------------------------------------------------------
__global__ __launch_bounds__(256, 4) void rotated_roi_pool_kernel(
    const float* __restrict__ obb,
    float* __restrict__ out)
{
    __shared__ int   o00[NPTS], o01[NPTS], o10[NPTS], o11[NPTS];
    __shared__ float w00s[NPTS], w01s[NPTS], w10s[NPTS], w11s[NPTS];
    __shared__ float tile[Sx * 132];                       // [64 points][132] floats

    const int t    = threadIdx.x;
    const int r    = blockIdx.y;
    const int b    = r >> 5;
    const int warp = t >> 5;
    const int lane = t & 31;

    // ---- Phase 0: per-sample-point coordinates, 128 points (2 sy rows) ----
    if (t < NPTS) {
        const int sx = t & 63;
        const int row = t >> 6;                  // 0..1
        const int sy = blockIdx.x * 2 + row;
        float cx, cy, wf, hf, c_, s_;
        roi_params(obb, r, cx, cy, wf, hf, c_, s_);

        const float sxs = wf * (2.0f / (float)WF);
        const float sys = hf * (2.0f / (float)HF);
        const float txc = cx * (2.0f / (float)WF) - 1.0f;
        const float tyc = cy * (2.0f / (float)HF) - 1.0f;
        const float a11 = c_ * sxs, a12 = -s_ * sys;
        const float a21 = s_ * sxs, a22 =  c_ * sys;

        const float X = 2.0f * ((float)sx + 0.5f) / (float)Sx - 1.0f;
        const float Y = 2.0f * ((float)sy + 0.5f) / (float)Sx - 1.0f;

        const float gx = a11 * X + a12 * Y + txc;
        const float gy = a21 * X + a22 * Y + tyc;

        const float ix = ((gx + 1.0f) * (float)WF - 1.0f) * 0.5f;
        const float iy = ((gy + 1.0f) * (float)HF - 1.0f) * 0.5f;

        const float x0f = floorf(ix);
        const float y0f = floorf(iy);
        const float wx = ix - x0f;
        const float wy = iy - y0f;

        const int x0 = (int)x0f, y0 = (int)y0f;
        const int x1 = x0 + 1,   y1 = y0 + 1;

        const float vx0 = (x0 >= 0 && x0 < WF) ? 1.0f : 0.0f;
        const float vx1 = (x1 >= 0 && x1 < WF) ? 1.0f : 0.0f;
        const float vy0 = (y0 >= 0 && y0 < HF) ? 1.0f : 0.0f;
        const float vy1 = (y1 >= 0 && y1 < HF) ? 1.0f : 0.0f;

        w00s[t] = (1.0f - wx) * (1.0f - wy) * vx0 * vy0;
        w01s[t] = wx          * (1.0f - wy) * vx1 * vy0;
        w10s[t] = (1.0f - wx) * wy          * vx0 * vy1;
        w11s[t] = wx          * wy          * vx1 * vy1;

        const int xc0 = min(max(x0, 0), WF - 1);
        const int xc1 = min(max(x1, 0), WF - 1);
        const int yc0 = min(max(y0, 0), HF - 1);
        const int yc1 = min(max(y1, 0), HF - 1);

        const int base = b * HF * WF;  // pixels
        o00[t] = (base + yc0 * WF + xc0) * (Cc / 4);
        o01[t] = (base + yc0 * WF + xc1) * (Cc / 4);
        o10[t] = (base + yc1 * WF + xc0) * (Cc / 4);
        o11[t] = (base + yc1 * WF + xc1) * (Cc / 4);
    }
    __syncthreads();

    const float4* __restrict__ nhwc4 = reinterpret_cast<const float4*>(g_nhwc);
    const int sx_st = t & 63;   // store-phase sx
    const int cg    = t >> 6;   // store-phase channel group (0..3)

    #pragma unroll
    for (int slab = 0; slab < 2; ++slab) {
        const int co = slab * 32 + lane;  // float4 chunk within pixel

        #pragma unroll
        for (int row = 0; row < 2; ++row) {
            const int ibase = row * 64 + warp * 8;

            // ---- compute phase: pipelined tap-reuse (R8 hot loop) ----
            {
                int p00 = o00[ibase], p01 = o01[ibase], p10 = o10[ibase], p11 = o11[ibase];
                float4 c00 = __ldg(&nhwc4[p00 + co]);
                float4 c01 = __ldg(&nhwc4[p01 + co]);
                float4 c10 = __ldg(&nhwc4[p10 + co]);
                float4 c11 = __ldg(&nhwc4[p11 + co]);

                #pragma unroll
                for (int j = 0; j < 8; ++j) {
                    const int i = ibase + j;

                    // Issue loads for point i+1 (consumed next iteration)
                    float4 n00, n01, n10, n11;
                    int mode = 0;
                    if (j < 7) {
                        const int u00 = o00[i + 1], u01 = o01[i + 1];
                        const int u10 = o10[i + 1], u11 = o11[i + 1];
                        if (u00 == p00 && u01 == p01 && u10 == p10 && u11 == p11) {
                            mode = 0;
                        } else if (u00 == p01 && u10 == p11) {
                            n01 = __ldg(&nhwc4[u01 + co]);
                            n11 = __ldg(&nhwc4[u11 + co]);
                            mode = 1;
                        } else if (u00 == p10 && u01 == p11) {
                            n10 = __ldg(&nhwc4[u10 + co]);
                            n11 = __ldg(&nhwc4[u11 + co]);
                            mode = 2;
                        } else {
                            n00 = __ldg(&nhwc4[u00 + co]);
                            n01 = __ldg(&nhwc4[u01 + co]);
                            n10 = __ldg(&nhwc4[u10 + co]);
                            n11 = __ldg(&nhwc4[u11 + co]);
                            mode = 3;
                        }
                        p00 = u00; p01 = u01; p10 = u10; p11 = u11;
                    }

                    const float a = w00s[i], b_ = w01s[i], c2 = w10s[i], d = w11s[i];
                    float4 v;
                    v.x = fmaf(d, c11.x, fmaf(c2, c10.x, fmaf(b_, c01.x, a * c00.x)));
                    v.y = fmaf(d, c11.y, fmaf(c2, c10.y, fmaf(b_, c01.y, a * c00.y)));
                    v.z = fmaf(d, c11.z, fmaf(c2, c10.z, fmaf(b_, c01.z, a * c00.z)));
                    v.w = fmaf(d, c11.w, fmaf(c2, c10.w, fmaf(b_, c01.w, a * c00.w)));
                    // tile row index is point-within-row (0..63)
                    *reinterpret_cast<float4*>(&tile[(i - row * 64) * 132 + 4 * lane]) = v;

                    if (j < 7) {
                        if (mode == 1)      { c00 = c01; c10 = c11; c01 = n01; c11 = n11; }
                        else if (mode == 2) { c00 = c10; c01 = c11; c10 = n10; c11 = n11; }
                        else if (mode == 3) { c00 = n00; c01 = n01; c10 = n10; c11 = n11; }
                    }
                }
            }
            __syncthreads();

            // ---- store phase: lanes = sx, coalesced streaming stores ----
            {
                const int sy = blockIdx.x * 2 + row;
                #pragma unroll
                for (int j = 0; j < 8; ++j) {
                    const int chunk = cg * 8 + j;          // 0..31
                    float4 v = *reinterpret_cast<const float4*>(&tile[sx_st * 132 + 4 * chunk]);
                    const int c_global = slab * 128 + 4 * chunk;
                    float* op = out + (((size_t)(r * Cc + c_global) * Sx + sy) * Sx) + sx_st;
                    __stcs(op,               v.x);
                    __stcs(op + 1 * Sx * Sx, v.y);
                    __stcs(op + 2 * Sx * Sx, v.z);
                    __stcs(op + 3 * Sx * Sx, v.w);
                }
            }
            __syncthreads();
        }
    }

    // ---- M_all (folded): block (blockIdx.x==0, r), one thread ----
    if (blockIdx.x == 0 && t == 0) {
        float cx, cy, wf, hf, c_, s_;
        roi_params(obb, r, cx, cy, wf, hf, c_, s_);
        const float A  =  c_ * (wf / (float)Sx);
        const float Bv = -s_ * (hf / (float)Sx);
        const float A2 =  s_ * (wf / (float)Sx);
        const float B2 =  c_ * (hf / (float)Sx);
        const float Cx = cx - 0.5f * (float)Sx * (A + Bv);
        const float Cy = cy - 0.5f * (float)Sx * (A2 + B2);
        float* o = out + CROPS_ELEMS + (size_t)r * 6;
        o[0] = A;  o[1] = Bv; o[2] = Cx;
        o[3] = A2; o[4] = B2; o[5] = Cy;
    }
}

extern "C" void kernel_launch(void* const* d_in, const int* in_sizes, int n_in,
                              void* d_out, int out_size) {
    const float* feat = (const float*)d_in[0];
    const float* obb  = (const float*)d_in[1];
    float* out = (float*)d_out;

    dim3 tb(8, 32, 1);
    dim3 tg(WF / 32, Cc / 32, Bn * HF / 4);   // (4, 8, 128)
    transpose_kernel<<<tg, tb>>>(feat);

    dim3 grid(Sx / 2, 128, 1);                // (sy-pair, roi) = (32, 128)
    rotated_roi_pool_kernel<<<grid, 256>>>(obb, out);
}

// round 15
// speedup vs baseline: 1.2417x; 1.2091x over previous
#include <cuda_runtime.h>
#include <cuda_fp16.h>

// Problem constants
#define Bn    4
#define Cc    256
#define HF    128
#define WF    128
#define Sx    64
#define CROPS_ELEMS ((size_t)128 * Cc * Sx * Sx)   // 134217728

// Scratch: feat transposed to NHWC [b][y][x][c], c contiguous, fp16 (33.5 MB)
__device__ __half g_nhwc[(size_t)Bn * HF * WF * Cc];

__device__ __forceinline__ void roi_params(const float* __restrict__ obb, int r,
                                           float& cx, float& cy, float& wf, float& hf,
                                           float& c_, float& s_) {
    const float* o = obb + r * 5;
    cx = o[0] * 0.125f;
    cy = o[1] * 0.125f;
    wf = fmaxf(o[2], 1.0f) * (1.25f / 8.0f);
    hf = fmaxf(o[3], 1.0f) * (1.25f / 8.0f);
    float ang = o[4] * 0.017453292519943295f;  // deg2rad
    c_ = cosf(ang);
    s_ = sinf(ang);
}

// half4 (uint2) -> float4
__device__ __forceinline__ float4 h4f(uint2 h) {
    float2 f0 = __half22float2(*reinterpret_cast<__half2*>(&h.x));
    float2 f1 = __half22float2(*reinterpret_cast<__half2*>(&h.y));
    return make_float4(f0.x, f0.y, f1.x, f1.y);
}

// ---------------------------------------------------------------------------
// Kernel 1: NCHW fp32 -> NHWC fp16 transpose, 4 y-rows per block.
// ---------------------------------------------------------------------------
__global__ __launch_bounds__(256) void transpose_kernel(const float* __restrict__ feat)
{
    __shared__ float ts[4][32 * 33];
    const int tx = threadIdx.x;       // 0..7
    const int ty = threadIdx.y;       // 0..31
    const int bz = blockIdx.z;        // 0..127
    const int b = bz >> 5;
    const int ybase = (bz & 31) * 4;

    const int c = blockIdx.y * 32 + ty;
    const float4* feat4 = reinterpret_cast<const float4*>(feat);
    const size_t rowbase = (size_t)(b * Cc + c) * HF;

    float4 v[4];
    #pragma unroll
    for (int k = 0; k < 4; ++k)
        v[k] = __ldcs(&feat4[(rowbase + ybase + k) * (WF / 4) + blockIdx.x * 8 + tx]);

    #pragma unroll
    for (int k = 0; k < 4; ++k) {
        ts[k][(4 * tx + 0) * 33 + ty] = v[k].x;
        ts[k][(4 * tx + 1) * 33 + ty] = v[k].y;
        ts[k][(4 * tx + 2) * 33 + ty] = v[k].z;
        ts[k][(4 * tx + 3) * 33 + ty] = v[k].w;
    }
    __syncthreads();

    uint2* nh = reinterpret_cast<uint2*>(g_nhwc);   // half4 units
    const int x = blockIdx.x * 32 + ty;
    #pragma unroll
    for (int k = 0; k < 4; ++k) {
        float4 o;
        o.x = ts[k][ty * 33 + 4 * tx + 0];
        o.y = ts[k][ty * 33 + 4 * tx + 1];
        o.z = ts[k][ty * 33 + 4 * tx + 2];
        o.w = ts[k][ty * 33 + 4 * tx + 3];
        __half2 h01 = __floats2half2_rn(o.x, o.y);
        __half2 h23 = __floats2half2_rn(o.z, o.w);
        uint2 hv;
        hv.x = *reinterpret_cast<unsigned int*>(&h01);
        hv.y = *reinterpret_cast<unsigned int*>(&h23);
        nh[((size_t)(b * HF + ybase + k) * WF + x) * (Cc / 4) + blockIdx.y * 8 + tx] = hv;
    }
}

// ---------------------------------------------------------------------------
// Kernel 2: pooling + M_all. One block per (roi, sy): 256 threads.
// R12-proven skeleton; taps are half4 (uint2) loads, fp32 weights/FMA.
// ---------------------------------------------------------------------------
__global__ __launch_bounds__(256, 4) void rotated_roi_pool_kernel(
    const float* __restrict__ obb,
    float* __restrict__ out)
{
    __shared__ int   o00[Sx], o01[Sx], o10[Sx], o11[Sx];   // half4-unit pixel bases
    __shared__ float w00s[Sx], w01s[Sx], w10s[Sx], w11s[Sx];
    __shared__ float tile[Sx * 132];                       // [point][132] floats

    const int t    = threadIdx.x;
    const int sy   = blockIdx.x;
    const int r    = blockIdx.y;
    const int b    = r >> 5;
    const int warp = t >> 5;
    const int lane = t & 31;

    // ---- Phase 0: per-sample-point coordinates ----
    if (t < Sx) {
        const int sx = t;
        float cx, cy, wf, hf, c_, s_;
        roi_params(obb, r, cx, cy, wf, hf, c_, s_);

        const float sxs = wf * (2.0f / (float)WF);
        const float sys = hf * (2.0f / (float)HF);
        const float txc = cx * (2.0f / (float)WF) - 1.0f;
        const float tyc = cy * (2.0f / (float)HF) - 1.0f;
        const float a11 = c_ * sxs, a12 = -s_ * sys;
        const float a21 = s_ * sxs, a22 =  c_ * sys;

        const float X = 2.0f * ((float)sx + 0.5f) / (float)Sx - 1.0f;
        const float Y = 2.0f * ((float)sy + 0.5f) / (float)Sx - 1.0f;

        const float gx = a11 * X + a12 * Y + txc;
        const float gy = a21 * X + a22 * Y + tyc;

        const float ix = ((gx + 1.0f) * (float)WF - 1.0f) * 0.5f;
        const float iy = ((gy + 1.0f) * (float)HF - 1.0f) * 0.5f;

        const float x0f = floorf(ix);
        const float y0f = floorf(iy);
        const float wx = ix - x0f;
        const float wy = iy - y0f;

        const int x0 = (int)x0f, y0 = (int)y0f;
        const int x1 = x0 + 1,   y1 = y0 + 1;

        const float vx0 = (x0 >= 0 && x0 < WF) ? 1.0f : 0.0f;
        const float vx1 = (x1 >= 0 && x1 < WF) ? 1.0f : 0.0f;
        const float vy0 = (y0 >= 0 && y0 < HF) ? 1.0f : 0.0f;
        const float vy1 = (y1 >= 0 && y1 < HF) ? 1.0f : 0.0f;

        w00s[sx] = (1.0f - wx) * (1.0f - wy) * vx0 * vy0;
        w01s[sx] = wx          * (1.0f - wy) * vx1 * vy0;
        w10s[sx] = (1.0f - wx) * wy          * vx0 * vy1;
        w11s[sx] = wx          * wy          * vx1 * vy1;

        const int xc0 = min(max(x0, 0), WF - 1);
        const int xc1 = min(max(x1, 0), WF - 1);
        const int yc0 = min(max(y0, 0), HF - 1);
        const int yc1 = min(max(y1, 0), HF - 1);

        const int base = b * HF * WF;  // pixels
        o00[sx] = (base + yc0 * WF + xc0) * (Cc / 4);
        o01[sx] = (base + yc0 * WF + xc1) * (Cc / 4);
        o10[sx] = (base + yc1 * WF + xc0) * (Cc / 4);
        o11[sx] = (base + yc1 * WF + xc1) * (Cc / 4);
    }
    __syncthreads();

    const uint2* __restrict__ nhwc = reinterpret_cast<const uint2*>(g_nhwc); // half4 units
    const int sx_st = t & 63;   // store-phase sx
    const int cg    = t >> 6;   // store-phase channel group (0..3)
    const int ibase = warp * 8;

    #pragma unroll
    for (int slab = 0; slab < 2; ++slab) {
        const int co = slab * 32 + lane;  // half4 chunk within pixel

        // ---- compute phase: pipelined tap-reuse (R8 hot loop, fp16 taps) ----
        int p00 = o00[ibase], p01 = o01[ibase], p10 = o10[ibase], p11 = o11[ibase];
        uint2 c00 = __ldg(&nhwc[p00 + co]);
        uint2 c01 = __ldg(&nhwc[p01 + co]);
        uint2 c10 = __ldg(&nhwc[p10 + co]);
        uint2 c11 = __ldg(&nhwc[p11 + co]);

        #pragma unroll
        for (int j = 0; j < 8; ++j) {
            const int i = ibase + j;

            // Issue loads for point i+1 (consumed next iteration)
            uint2 n00, n01, n10, n11;
            int mode = 0;
            if (j < 7) {
                const int u00 = o00[i + 1], u01 = o01[i + 1];
                const int u10 = o10[i + 1], u11 = o11[i + 1];
                if (u00 == p00 && u01 == p01 && u10 == p10 && u11 == p11) {
                    mode = 0;
                } else if (u00 == p01 && u10 == p11) {
                    n01 = __ldg(&nhwc[u01 + co]);
                    n11 = __ldg(&nhwc[u11 + co]);
                    mode = 1;
                } else if (u00 == p10 && u01 == p11) {
                    n10 = __ldg(&nhwc[u10 + co]);
                    n11 = __ldg(&nhwc[u11 + co]);
                    mode = 2;
                } else {
                    n00 = __ldg(&nhwc[u00 + co]);
                    n01 = __ldg(&nhwc[u01 + co]);
                    n10 = __ldg(&nhwc[u10 + co]);
                    n11 = __ldg(&nhwc[u11 + co]);
                    mode = 3;
                }
                p00 = u00; p01 = u01; p10 = u10; p11 = u11;
            }

            const float a = w00s[i], b_ = w01s[i], c2 = w10s[i], d = w11s[i];
            const float4 f00 = h4f(c00), f01 = h4f(c01), f10 = h4f(c10), f11 = h4f(c11);
            float4 v;
            v.x = fmaf(d, f11.x, fmaf(c2, f10.x, fmaf(b_, f01.x, a * f00.x)));
            v.y = fmaf(d, f11.y, fmaf(c2, f10.y, fmaf(b_, f01.y, a * f00.y)));
            v.z = fmaf(d, f11.z, fmaf(c2, f10.z, fmaf(b_, f01.z, a * f00.z)));
            v.w = fmaf(d, f11.w, fmaf(c2, f10.w, fmaf(b_, f01.w, a * f00.w)));
            *reinterpret_cast<float4*>(&tile[i * 132 + 4 * lane]) = v;

            if (j < 7) {
                if (mode == 1)      { c00 = c01; c10 = c11; c01 = n01; c11 = n11; }
                else if (mode == 2) { c00 = c10; c01 = c11; c10 = n10; c11 = n11; }
                else if (mode == 3) { c00 = n00; c01 = n01; c10 = n10; c11 = n11; }
            }
        }
        __syncthreads();

        // ---- store phase: lanes = sx, coalesced streaming stores ----
        #pragma unroll
        for (int j = 0; j < 8; ++j) {
            const int chunk = cg * 8 + j;          // 0..31
            float4 v = *reinterpret_cast<const float4*>(&tile[sx_st * 132 + 4 * chunk]);
            const int c_global = slab * 128 + 4 * chunk;
            float* op = out + (((size_t)(r * Cc + c_global) * Sx + sy) * Sx) + sx_st;
            __stcs(op,               v.x);
            __stcs(op + 1 * Sx * Sx, v.y);
            __stcs(op + 2 * Sx * Sx, v.z);
            __stcs(op + 3 * Sx * Sx, v.w);
        }
        __syncthreads();
    }

    // ---- M_all (folded, full fp32): block (sy==0, r), one thread ----
    if (sy == 0 && t == 0) {
        float cx, cy, wf, hf, c_, s_;
        roi_params(obb, r, cx, cy, wf, hf, c_, s_);
        const float A  =  c_ * (wf / (float)Sx);
        const float Bv = -s_ * (hf / (float)Sx);
        const float A2 =  s_ * (wf / (float)Sx);
        const float B2 =  c_ * (hf / (float)Sx);
        const float Cx = cx - 0.5f * (float)Sx * (A + Bv);
        const float Cy = cy - 0.5f * (float)Sx * (A2 + B2);
        float* o = out + CROPS_ELEMS + (size_t)r * 6;
        o[0] = A;  o[1] = Bv; o[2] = Cx;
        o[3] = A2; o[4] = B2; o[5] = Cy;
    }
}

extern "C" void kernel_launch(void* const* d_in, const int* in_sizes, int n_in,
                              void* d_out, int out_size) {
    const float* feat = (const float*)d_in[0];
    const float* obb  = (const float*)d_in[1];
    float* out = (float*)d_out;

    dim3 tb(8, 32, 1);
    dim3 tg(WF / 32, Cc / 32, Bn * HF / 4);   // (4, 8, 128)
    transpose_kernel<<<tg, tb>>>(feat);

    dim3 grid(Sx, 128, 1);                    // (sy, roi)
    rotated_roi_pool_kernel<<<grid, 256>>>(obb, out);
}

// round 16
// speedup vs baseline: 1.4129x; 1.1379x over previous
#include <cuda_runtime.h>
#include <cuda_fp16.h>

// Problem constants
#define Bn    4
#define Cc    256
#define HF    128
#define WF    128
#define Sx    64
#define CROPS_ELEMS ((size_t)128 * Cc * Sx * Sx)   // 134217728
#define TRW   33    // tile row stride in uint2 units (32 chunks + 1 pad = 264B)

// Scratch: feat transposed to NHWC [b][y][x][c], c contiguous, fp16 (33.5 MB)
__device__ __half g_nhwc[(size_t)Bn * HF * WF * Cc];

__device__ __forceinline__ void roi_params(const float* __restrict__ obb, int r,
                                           float& cx, float& cy, float& wf, float& hf,
                                           float& c_, float& s_) {
    const float* o = obb + r * 5;
    cx = o[0] * 0.125f;
    cy = o[1] * 0.125f;
    wf = fmaxf(o[2], 1.0f) * (1.25f / 8.0f);
    hf = fmaxf(o[3], 1.0f) * (1.25f / 8.0f);
    float ang = o[4] * 0.017453292519943295f;  // deg2rad
    c_ = cosf(ang);
    s_ = sinf(ang);
}

__device__ __forceinline__ __half2 u2h(unsigned int u) {
    return *reinterpret_cast<__half2*>(&u);
}
__device__ __forceinline__ unsigned int h2u(__half2 h) {
    return *reinterpret_cast<unsigned int*>(&h);
}

// ---------------------------------------------------------------------------
// Kernel 1: NCHW fp32 -> NHWC fp16 transpose, 4 y-rows per block. Proven.
// ---------------------------------------------------------------------------
__global__ __launch_bounds__(256) void transpose_kernel(const float* __restrict__ feat)
{
    __shared__ float ts[4][32 * 33];
    const int tx = threadIdx.x;       // 0..7
    const int ty = threadIdx.y;       // 0..31
    const int bz = blockIdx.z;        // 0..127
    const int b = bz >> 5;
    const int ybase = (bz & 31) * 4;

    const int c = blockIdx.y * 32 + ty;
    const float4* feat4 = reinterpret_cast<const float4*>(feat);
    const size_t rowbase = (size_t)(b * Cc + c) * HF;

    float4 v[4];
    #pragma unroll
    for (int k = 0; k < 4; ++k)
        v[k] = __ldcs(&feat4[(rowbase + ybase + k) * (WF / 4) + blockIdx.x * 8 + tx]);

    #pragma unroll
    for (int k = 0; k < 4; ++k) {
        ts[k][(4 * tx + 0) * 33 + ty] = v[k].x;
        ts[k][(4 * tx + 1) * 33 + ty] = v[k].y;
        ts[k][(4 * tx + 2) * 33 + ty] = v[k].z;
        ts[k][(4 * tx + 3) * 33 + ty] = v[k].w;
    }
    __syncthreads();

    uint2* nh = reinterpret_cast<uint2*>(g_nhwc);   // half4 units
    const int x = blockIdx.x * 32 + ty;
    #pragma unroll
    for (int k = 0; k < 4; ++k) {
        float4 o;
        o.x = ts[k][ty * 33 + 4 * tx + 0];
        o.y = ts[k][ty * 33 + 4 * tx + 1];
        o.z = ts[k][ty * 33 + 4 * tx + 2];
        o.w = ts[k][ty * 33 + 4 * tx + 3];
        uint2 hv;
        hv.x = h2u(__floats2half2_rn(o.x, o.y));
        hv.y = h2u(__floats2half2_rn(o.z, o.w));
        nh[((size_t)(b * HF + ybase + k) * WF + x) * (Cc / 4) + blockIdx.y * 8 + tx] = hv;
    }
}

// ---------------------------------------------------------------------------
// Kernel 2: pooling + M_all. One block per (roi, sy): 256 threads.
// Full-fp16 bridge: half4 taps, half2 weights, HFMA2 accumulate, fp16 tile
// (STS.64/LDS.64), fp32 conversion only at the final coalesced STG.
// ---------------------------------------------------------------------------
__global__ __launch_bounds__(256, 4) void rotated_roi_pool_kernel(
    const float* __restrict__ obb,
    float* __restrict__ out)
{
    __shared__ int          o00[Sx], o01[Sx], o10[Sx], o11[Sx];  // half4-unit bases
    __shared__ unsigned int w00h[Sx], w01h[Sx], w10h[Sx], w11h[Sx]; // half2 weights
    __shared__ uint2        tile[Sx * TRW];                      // [point][33] half4

    const int t    = threadIdx.x;
    const int sy   = blockIdx.x;
    const int r    = blockIdx.y;
    const int b    = r >> 5;
    const int warp = t >> 5;
    const int lane = t & 31;

    // ---- Phase 0: per-sample-point coordinates ----
    if (t < Sx) {
        const int sx = t;
        float cx, cy, wf, hf, c_, s_;
        roi_params(obb, r, cx, cy, wf, hf, c_, s_);

        const float sxs = wf * (2.0f / (float)WF);
        const float sys = hf * (2.0f / (float)HF);
        const float txc = cx * (2.0f / (float)WF) - 1.0f;
        const float tyc = cy * (2.0f / (float)HF) - 1.0f;
        const float a11 = c_ * sxs, a12 = -s_ * sys;
        const float a21 = s_ * sxs, a22 =  c_ * sys;

        const float X = 2.0f * ((float)sx + 0.5f) / (float)Sx - 1.0f;
        const float Y = 2.0f * ((float)sy + 0.5f) / (float)Sx - 1.0f;

        const float gx = a11 * X + a12 * Y + txc;
        const float gy = a21 * X + a22 * Y + tyc;

        const float ix = ((gx + 1.0f) * (float)WF - 1.0f) * 0.5f;
        const float iy = ((gy + 1.0f) * (float)HF - 1.0f) * 0.5f;

        const float x0f = floorf(ix);
        const float y0f = floorf(iy);
        const float wx = ix - x0f;
        const float wy = iy - y0f;

        const int x0 = (int)x0f, y0 = (int)y0f;
        const int x1 = x0 + 1,   y1 = y0 + 1;

        const float vx0 = (x0 >= 0 && x0 < WF) ? 1.0f : 0.0f;
        const float vx1 = (x1 >= 0 && x1 < WF) ? 1.0f : 0.0f;
        const float vy0 = (y0 >= 0 && y0 < HF) ? 1.0f : 0.0f;
        const float vy1 = (y1 >= 0 && y1 < HF) ? 1.0f : 0.0f;

        const float W00 = (1.0f - wx) * (1.0f - wy) * vx0 * vy0;
        const float W01 = wx          * (1.0f - wy) * vx1 * vy0;
        const float W10 = (1.0f - wx) * wy          * vx0 * vy1;
        const float W11 = wx          * wy          * vx1 * vy1;

        w00h[sx] = h2u(__float2half2_rn(W00));
        w01h[sx] = h2u(__float2half2_rn(W01));
        w10h[sx] = h2u(__float2half2_rn(W10));
        w11h[sx] = h2u(__float2half2_rn(W11));

        const int xc0 = min(max(x0, 0), WF - 1);
        const int xc1 = min(max(x1, 0), WF - 1);
        const int yc0 = min(max(y0, 0), HF - 1);
        const int yc1 = min(max(y1, 0), HF - 1);

        const int base = b * HF * WF;  // pixels
        o00[sx] = (base + yc0 * WF + xc0) * (Cc / 4);
        o01[sx] = (base + yc0 * WF + xc1) * (Cc / 4);
        o10[sx] = (base + yc1 * WF + xc0) * (Cc / 4);
        o11[sx] = (base + yc1 * WF + xc1) * (Cc / 4);
    }
    __syncthreads();

    const uint2* __restrict__ nhwc = reinterpret_cast<const uint2*>(g_nhwc); // half4 units
    const int sx_st = t & 63;   // store-phase sx
    const int cg    = t >> 6;   // store-phase channel group (0..3)
    const int ibase = warp * 8;

    #pragma unroll
    for (int slab = 0; slab < 2; ++slab) {
        const int co = slab * 32 + lane;  // half4 chunk within pixel

        // ---- compute phase: pipelined tap-reuse, HFMA2 accumulate ----
        int p00 = o00[ibase], p01 = o01[ibase], p10 = o10[ibase], p11 = o11[ibase];
        uint2 c00 = __ldg(&nhwc[p00 + co]);
        uint2 c01 = __ldg(&nhwc[p01 + co]);
        uint2 c10 = __ldg(&nhwc[p10 + co]);
        uint2 c11 = __ldg(&nhwc[p11 + co]);

        #pragma unroll
        for (int j = 0; j < 8; ++j) {
            const int i = ibase + j;

            // Issue loads for point i+1 (consumed next iteration)
            uint2 n00, n01, n10, n11;
            int mode = 0;
            if (j < 7) {
                const int u00 = o00[i + 1], u01 = o01[i + 1];
                const int u10 = o10[i + 1], u11 = o11[i + 1];
                if (u00 == p00 && u01 == p01 && u10 == p10 && u11 == p11) {
                    mode = 0;
                } else if (u00 == p01 && u10 == p11) {
                    n01 = __ldg(&nhwc[u01 + co]);
                    n11 = __ldg(&nhwc[u11 + co]);
                    mode = 1;
                } else if (u00 == p10 && u01 == p11) {
                    n10 = __ldg(&nhwc[u10 + co]);
                    n11 = __ldg(&nhwc[u11 + co]);
                    mode = 2;
                } else {
                    n00 = __ldg(&nhwc[u00 + co]);
                    n01 = __ldg(&nhwc[u01 + co]);
                    n10 = __ldg(&nhwc[u10 + co]);
                    n11 = __ldg(&nhwc[u11 + co]);
                    mode = 3;
                }
                p00 = u00; p01 = u01; p10 = u10; p11 = u11;
            }

            const __half2 a  = u2h(w00h[i]);
            const __half2 bb = u2h(w01h[i]);
            const __half2 cc = u2h(w10h[i]);
            const __half2 dd = u2h(w11h[i]);

            __half2 lo = __hmul2(a, u2h(c00.x));
            lo = __hfma2(bb, u2h(c01.x), lo);
            lo = __hfma2(cc, u2h(c10.x), lo);
            lo = __hfma2(dd, u2h(c11.x), lo);
            __half2 hi = __hmul2(a, u2h(c00.y));
            hi = __hfma2(bb, u2h(c01.y), hi);
            hi = __hfma2(cc, u2h(c10.y), hi);
            hi = __hfma2(dd, u2h(c11.y), hi);

            uint2 v;
            v.x = h2u(lo);
            v.y = h2u(hi);
            tile[i * TRW + lane] = v;    // STS.64, conflict-free

            if (j < 7) {
                if (mode == 1)      { c00 = c01; c10 = c11; c01 = n01; c11 = n11; }
                else if (mode == 2) { c00 = c10; c01 = c11; c10 = n10; c11 = n11; }
                else if (mode == 3) { c00 = n00; c01 = n01; c10 = n10; c11 = n11; }
            }
        }
        __syncthreads();

        // ---- store phase: lanes = sx; fp16->fp32 convert + coalesced STG ----
        #pragma unroll
        for (int j = 0; j < 8; ++j) {
            const int chunk = cg * 8 + j;          // 0..31
            uint2 v = tile[sx_st * TRW + chunk];   // LDS.64, conflict-free
            float2 f0 = __half22float2(u2h(v.x));
            float2 f1 = __half22float2(u2h(v.y));
            const int c_global = slab * 128 + 4 * chunk;
            float* op = out + (((size_t)(r * Cc + c_global) * Sx + sy) * Sx) + sx_st;
            __stcs(op,               f0.x);
            __stcs(op + 1 * Sx * Sx, f0.y);
            __stcs(op + 2 * Sx * Sx, f1.x);
            __stcs(op + 3 * Sx * Sx, f1.y);
        }
        __syncthreads();
    }

    // ---- M_all (folded, full fp32): block (sy==0, r), one thread ----
    if (sy == 0 && t == 0) {
        float cx, cy, wf, hf, c_, s_;
        roi_params(obb, r, cx, cy, wf, hf, c_, s_);
        const float A  =  c_ * (wf / (float)Sx);
        const float Bv = -s_ * (hf / (float)Sx);
        const float A2 =  s_ * (wf / (float)Sx);
        const float B2 =  c_ * (hf / (float)Sx);
        const float Cx = cx - 0.5f * (float)Sx * (A + Bv);
        const float Cy = cy - 0.5f * (float)Sx * (A2 + B2);
        float* o = out + CROPS_ELEMS + (size_t)r * 6;
        o[0] = A;  o[1] = Bv; o[2] = Cx;
        o[3] = A2; o[4] = B2; o[5] = Cy;
    }
}

extern "C" void kernel_launch(void* const* d_in, const int* in_sizes, int n_in,
                              void* d_out, int out_size) {
    const float* feat = (const float*)d_in[0];
    const float* obb  = (const float*)d_in[1];
    float* out = (float*)d_out;

    dim3 tb(8, 32, 1);
    dim3 tg(WF / 32, Cc / 32, Bn * HF / 4);   // (4, 8, 128)
    transpose_kernel<<<tg, tb>>>(feat);

    dim3 grid(Sx, 128, 1);                    // (sy, roi)
    rotated_roi_pool_kernel<<<grid, 256>>>(obb, out);
}

// round 17
// speedup vs baseline: 1.4178x; 1.0035x over previous
#include <cuda_runtime.h>
#include <cuda_fp16.h>

// Problem constants
#define Bn    4
#define Cc    256
#define HF    128
#define WF    128
#define Sx    64
#define CROPS_ELEMS ((size_t)128 * Cc * Sx * Sx)   // 134217728
#define TRW   33    // tile row stride in uint2 units (32 chunks + 1 pad)

// Scratch: feat transposed to NHWC [b][y][x][c], c contiguous, fp16 (33.5 MB)
__device__ __half g_nhwc[(size_t)Bn * HF * WF * Cc];

__device__ __forceinline__ void roi_params(const float* __restrict__ obb, int r,
                                           float& cx, float& cy, float& wf, float& hf,
                                           float& c_, float& s_) {
    const float* o = obb + r * 5;
    cx = o[0] * 0.125f;
    cy = o[1] * 0.125f;
    wf = fmaxf(o[2], 1.0f) * (1.25f / 8.0f);
    hf = fmaxf(o[3], 1.0f) * (1.25f / 8.0f);
    float ang = o[4] * 0.017453292519943295f;  // deg2rad
    c_ = cosf(ang);
    s_ = sinf(ang);
}

__device__ __forceinline__ __half2 u2h(unsigned int u) {
    return *reinterpret_cast<__half2*>(&u);
}
__device__ __forceinline__ unsigned int h2u(__half2 h) {
    return *reinterpret_cast<unsigned int*>(&h);
}

// ---------------------------------------------------------------------------
// Kernel 1: NCHW fp32 -> NHWC fp16 transpose, 4 y-rows per block. Proven.
// ---------------------------------------------------------------------------
__global__ __launch_bounds__(256) void transpose_kernel(const float* __restrict__ feat)
{
    __shared__ float ts[4][32 * 33];
    const int tx = threadIdx.x;       // 0..7
    const int ty = threadIdx.y;       // 0..31
    const int bz = blockIdx.z;        // 0..127
    const int b = bz >> 5;
    const int ybase = (bz & 31) * 4;

    const int c = blockIdx.y * 32 + ty;
    const float4* feat4 = reinterpret_cast<const float4*>(feat);
    const size_t rowbase = (size_t)(b * Cc + c) * HF;

    float4 v[4];
    #pragma unroll
    for (int k = 0; k < 4; ++k)
        v[k] = __ldcs(&feat4[(rowbase + ybase + k) * (WF / 4) + blockIdx.x * 8 + tx]);

    #pragma unroll
    for (int k = 0; k < 4; ++k) {
        ts[k][(4 * tx + 0) * 33 + ty] = v[k].x;
        ts[k][(4 * tx + 1) * 33 + ty] = v[k].y;
        ts[k][(4 * tx + 2) * 33 + ty] = v[k].z;
        ts[k][(4 * tx + 3) * 33 + ty] = v[k].w;
    }
    __syncthreads();

    uint2* nh = reinterpret_cast<uint2*>(g_nhwc);   // half4 units
    const int x = blockIdx.x * 32 + ty;
    #pragma unroll
    for (int k = 0; k < 4; ++k) {
        float4 o;
        o.x = ts[k][ty * 33 + 4 * tx + 0];
        o.y = ts[k][ty * 33 + 4 * tx + 1];
        o.z = ts[k][ty * 33 + 4 * tx + 2];
        o.w = ts[k][ty * 33 + 4 * tx + 3];
        uint2 hv;
        hv.x = h2u(__floats2half2_rn(o.x, o.y));
        hv.y = h2u(__floats2half2_rn(o.z, o.w));
        nh[((size_t)(b * HF + ybase + k) * WF + x) * (Cc / 4) + blockIdx.y * 8 + tx] = hv;
    }
}

// ---------------------------------------------------------------------------
// Pipelined tap-reuse HFMA2 compute for one slab (8 points per warp).
// Taps arrive preloaded so the caller can prefetch across phases.
// ---------------------------------------------------------------------------
__device__ __forceinline__ void compute_slab(
    const uint2* __restrict__ nhwc,
    const int* o00, const int* o01, const int* o10, const int* o11,
    const unsigned int* w00h, const unsigned int* w01h,
    const unsigned int* w10h, const unsigned int* w11h,
    uint2* tile, int ibase, int co, int lane,
    int p00, int p01, int p10, int p11,
    uint2 c00, uint2 c01, uint2 c10, uint2 c11)
{
    #pragma unroll
    for (int j = 0; j < 8; ++j) {
        const int i = ibase + j;

        uint2 n00, n01, n10, n11;
        int mode = 0;
        if (j < 7) {
            const int u00 = o00[i + 1], u01 = o01[i + 1];
            const int u10 = o10[i + 1], u11 = o11[i + 1];
            if (u00 == p00 && u01 == p01 && u10 == p10 && u11 == p11) {
                mode = 0;
            } else if (u00 == p01 && u10 == p11) {
                n01 = __ldg(&nhwc[u01 + co]);
                n11 = __ldg(&nhwc[u11 + co]);
                mode = 1;
            } else if (u00 == p10 && u01 == p11) {
                n10 = __ldg(&nhwc[u10 + co]);
                n11 = __ldg(&nhwc[u11 + co]);
                mode = 2;
            } else {
                n00 = __ldg(&nhwc[u00 + co]);
                n01 = __ldg(&nhwc[u01 + co]);
                n10 = __ldg(&nhwc[u10 + co]);
                n11 = __ldg(&nhwc[u11 + co]);
                mode = 3;
            }
            p00 = u00; p01 = u01; p10 = u10; p11 = u11;
        }

        const __half2 a  = u2h(w00h[i]);
        const __half2 bb = u2h(w01h[i]);
        const __half2 cc = u2h(w10h[i]);
        const __half2 dd = u2h(w11h[i]);

        __half2 lo = __hmul2(a, u2h(c00.x));
        lo = __hfma2(bb, u2h(c01.x), lo);
        lo = __hfma2(cc, u2h(c10.x), lo);
        lo = __hfma2(dd, u2h(c11.x), lo);
        __half2 hi = __hmul2(a, u2h(c00.y));
        hi = __hfma2(bb, u2h(c01.y), hi);
        hi = __hfma2(cc, u2h(c10.y), hi);
        hi = __hfma2(dd, u2h(c11.y), hi);

        uint2 v;
        v.x = h2u(lo);
        v.y = h2u(hi);
        tile[i * TRW + lane] = v;    // STS.64, conflict-free

        if (j < 7) {
            if (mode == 1)      { c00 = c01; c10 = c11; c01 = n01; c11 = n11; }
            else if (mode == 2) { c00 = c10; c01 = c11; c10 = n10; c11 = n11; }
            else if (mode == 3) { c00 = n00; c01 = n01; c10 = n10; c11 = n11; }
        }
    }
}

__device__ __forceinline__ void store_slab(
    const uint2* tile, float* __restrict__ out,
    int r, int sy, int slab, int sx_st, int cg)
{
    #pragma unroll
    for (int j = 0; j < 8; ++j) {
        const int chunk = cg * 8 + j;          // 0..31
        uint2 v = tile[sx_st * TRW + chunk];   // LDS.64, conflict-free
        float2 f0 = __half22float2(u2h(v.x));
        float2 f1 = __half22float2(u2h(v.y));
        const int c_global = slab * 128 + 4 * chunk;
        float* op = out + (((size_t)(r * Cc + c_global) * Sx + sy) * Sx) + sx_st;
        __stcs(op,               f0.x);
        __stcs(op + 1 * Sx * Sx, f0.y);
        __stcs(op + 2 * Sx * Sx, f1.x);
        __stcs(op + 3 * Sx * Sx, f1.y);
    }
}

// ---------------------------------------------------------------------------
// Kernel 2: pooling + M_all. One block per (roi, sy): 256 threads.
// Double-buffered fp16 tiles: store(slab0) overlaps compute(slab1)'s loads,
// so the DRAM write drain and the L1 gather work run concurrently.
// ---------------------------------------------------------------------------
__global__ __launch_bounds__(256, 4) void rotated_roi_pool_kernel(
    const float* __restrict__ obb,
    float* __restrict__ out)
{
    __shared__ int          o00[Sx], o01[Sx], o10[Sx], o11[Sx];
    __shared__ unsigned int w00h[Sx], w01h[Sx], w10h[Sx], w11h[Sx];
    __shared__ uint2        tile0[Sx * TRW];
    __shared__ uint2        tile1[Sx * TRW];

    const int t    = threadIdx.x;
    const int sy   = blockIdx.x;
    const int r    = blockIdx.y;
    const int b    = r >> 5;
    const int warp = t >> 5;
    const int lane = t & 31;

    // ---- Phase 0: per-sample-point coordinates ----
    if (t < Sx) {
        const int sx = t;
        float cx, cy, wf, hf, c_, s_;
        roi_params(obb, r, cx, cy, wf, hf, c_, s_);

        const float sxs = wf * (2.0f / (float)WF);
        const float sys = hf * (2.0f / (float)HF);
        const float txc = cx * (2.0f / (float)WF) - 1.0f;
        const float tyc = cy * (2.0f / (float)HF) - 1.0f;
        const float a11 = c_ * sxs, a12 = -s_ * sys;
        const float a21 = s_ * sxs, a22 =  c_ * sys;

        const float X = 2.0f * ((float)sx + 0.5f) / (float)Sx - 1.0f;
        const float Y = 2.0f * ((float)sy + 0.5f) / (float)Sx - 1.0f;

        const float gx = a11 * X + a12 * Y + txc;
        const float gy = a21 * X + a22 * Y + tyc;

        const float ix = ((gx + 1.0f) * (float)WF - 1.0f) * 0.5f;
        const float iy = ((gy + 1.0f) * (float)HF - 1.0f) * 0.5f;

        const float x0f = floorf(ix);
        const float y0f = floorf(iy);
        const float wx = ix - x0f;
        const float wy = iy - y0f;

        const int x0 = (int)x0f, y0 = (int)y0f;
        const int x1 = x0 + 1,   y1 = y0 + 1;

        const float vx0 = (x0 >= 0 && x0 < WF) ? 1.0f : 0.0f;
        const float vx1 = (x1 >= 0 && x1 < WF) ? 1.0f : 0.0f;
        const float vy0 = (y0 >= 0 && y0 < HF) ? 1.0f : 0.0f;
        const float vy1 = (y1 >= 0 && y1 < HF) ? 1.0f : 0.0f;

        const float W00 = (1.0f - wx) * (1.0f - wy) * vx0 * vy0;
        const float W01 = wx          * (1.0f - wy) * vx1 * vy0;
        const float W10 = (1.0f - wx) * wy          * vx0 * vy1;
        const float W11 = wx          * wy          * vx1 * vy1;

        w00h[sx] = h2u(__float2half2_rn(W00));
        w01h[sx] = h2u(__float2half2_rn(W01));
        w10h[sx] = h2u(__float2half2_rn(W10));
        w11h[sx] = h2u(__float2half2_rn(W11));

        const int xc0 = min(max(x0, 0), WF - 1);
        const int xc1 = min(max(x1, 0), WF - 1);
        const int yc0 = min(max(y0, 0), HF - 1);
        const int yc1 = min(max(y1, 0), HF - 1);

        const int base = b * HF * WF;  // pixels
        o00[sx] = (base + yc0 * WF + xc0) * (Cc / 4);
        o01[sx] = (base + yc0 * WF + xc1) * (Cc / 4);
        o10[sx] = (base + yc1 * WF + xc0) * (Cc / 4);
        o11[sx] = (base + yc1 * WF + xc1) * (Cc / 4);
    }
    __syncthreads();

    const uint2* __restrict__ nhwc = reinterpret_cast<const uint2*>(g_nhwc);
    const int sx_st = t & 63;
    const int cg    = t >> 6;
    const int ibase = warp * 8;

    // ---- slab 0 compute -> tile0 ----
    {
        const int co = lane;
        const int p00 = o00[ibase], p01 = o01[ibase], p10 = o10[ibase], p11 = o11[ibase];
        uint2 c00 = __ldg(&nhwc[p00 + co]);
        uint2 c01 = __ldg(&nhwc[p01 + co]);
        uint2 c10 = __ldg(&nhwc[p10 + co]);
        uint2 c11 = __ldg(&nhwc[p11 + co]);
        compute_slab(nhwc, o00, o01, o10, o11, w00h, w01h, w10h, w11h,
                     tile0, ibase, co, lane, p00, p01, p10, p11, c00, c01, c10, c11);
    }
    __syncthreads();

    // ---- prefetch slab 1's first taps (fly during store0) ----
    const int co1 = 32 + lane;
    const int q00 = o00[ibase], q01 = o01[ibase], q10 = o10[ibase], q11 = o11[ibase];
    uint2 d00 = __ldg(&nhwc[q00 + co1]);
    uint2 d01 = __ldg(&nhwc[q01 + co1]);
    uint2 d10 = __ldg(&nhwc[q10 + co1]);
    uint2 d11 = __ldg(&nhwc[q11 + co1]);

    // ---- store slab 0 (DRAM drain overlaps the prefetch + compute1) ----
    store_slab(tile0, out, r, sy, 0, sx_st, cg);

    // ---- slab 1 compute -> tile1 (no sync: different buffer) ----
    compute_slab(nhwc, o00, o01, o10, o11, w00h, w01h, w10h, w11h,
                 tile1, ibase, co1, lane, q00, q01, q10, q11, d00, d01, d10, d11);
    __syncthreads();

    // ---- store slab 1 ----
    store_slab(tile1, out, r, sy, 1, sx_st, cg);

    // ---- M_all (folded, full fp32): block (sy==0, r), one thread ----
    if (sy == 0 && t == 0) {
        float cx, cy, wf, hf, c_, s_;
        roi_params(obb, r, cx, cy, wf, hf, c_, s_);
        const float A  =  c_ * (wf / (float)Sx);
        const float Bv = -s_ * (hf / (float)Sx);
        const float A2 =  s_ * (wf / (float)Sx);
        const float B2 =  c_ * (hf / (float)Sx);
        const float Cx = cx - 0.5f * (float)Sx * (A + Bv);
        const float Cy = cy - 0.5f * (float)Sx * (A2 + B2);
        float* o = out + CROPS_ELEMS + (size_t)r * 6;
        o[0] = A;  o[1] = Bv; o[2] = Cx;
        o[3] = A2; o[4] = B2; o[5] = Cy;
    }
}

extern "C" void kernel_launch(void* const* d_in, const int* in_sizes, int n_in,
                              void* d_out, int out_size) {
    const float* feat = (const float*)d_in[0];
    const float* obb  = (const float*)d_in[1];
    float* out = (float*)d_out;

    dim3 tb(8, 32, 1);
    dim3 tg(WF / 32, Cc / 32, Bn * HF / 4);   // (4, 8, 128)
    transpose_kernel<<<tg, tb>>>(feat);

    dim3 grid(Sx, 128, 1);                    // (sy, roi)
    rotated_roi_pool_kernel<<<grid, 256>>>(obb, out);
}